// round 3
// baseline (speedup 1.0000x reference)
#include <cuda_runtime.h>

typedef unsigned long long u64;

#define NTHREADS 128

#define SDIM   3
#define LDIM   4
#define IDIM   3
#define TOT    7
#define SUDIM  10
#define HIDL   64
#define HIDB   32
#define DT_F   0.01f

// Duplicated-pair shared layout (float offsets). All row strides are multiples
// of 4 floats (16B) and all bases are 16B-aligned.
#define W1D    0        // 64 rows x 24 floats: [10 w-pairs][b1 pair][pad pair]
#define W2TD   1536     // 64 rows x 8  floats: [4 pairs: W2[0..3][j]]
#define WZD    2048     // 7 rows x 24 floats: [10 w-pairs][bz pair][pad pair]
#define WB1D   2216     // 96 rows x 16 floats: [6 w-pairs][bb1 pair][wb2 pair]
#define PHYSD  3752     // 3 rows x 12 floats: [A row 3 pairs][Bm row 3 pairs]
#define CD     3788     // 3 rows x 8 floats:  [C row 3 pairs][zero pad pair]
#define B2D    3812     // 4 pairs
#define BB2D   3820     // 3 pairs
#define W_TOTAL 3828    // floats (~15.3 KB)

__device__ __forceinline__ u64 pack2(float lo, float hi) {
    u64 r; asm("mov.b64 %0, {%1, %2};" : "=l"(r) : "f"(lo), "f"(hi)); return r;
}
__device__ __forceinline__ void unpack2(u64 v, float& lo, float& hi) {
    asm("mov.b64 {%0, %1}, %2;" : "=f"(lo), "=f"(hi) : "l"(v));
}
__device__ __forceinline__ u64 ffma2(u64 a, u64 b, u64 c) {
    u64 d; asm("fma.rn.f32x2 %0, %1, %2, %3;" : "=l"(d) : "l"(a), "l"(b), "l"(c));
    return d;
}
__device__ __forceinline__ float fast_tanh(float x) {
    float r; asm("tanh.approx.f32 %0, %1;" : "=f"(r) : "f"(x)); return r;
}
__device__ __forceinline__ u64 tanh2(u64 v) {
    float lo, hi; unpack2(v, lo, hi);
    return pack2(fast_tanh(lo), fast_tanh(hi));
}

__global__ void __launch_bounds__(NTHREADS, 7)
phygru_kernel(const float* __restrict__ state,
              const float* __restrict__ u,
              const float* __restrict__ gA,  const float* __restrict__ gBm,
              const float* __restrict__ gC,  const float* __restrict__ gWz,
              const float* __restrict__ gbz, const float* __restrict__ gW1,
              const float* __restrict__ gb1, const float* __restrict__ gW2,
              const float* __restrict__ gb2, const float* __restrict__ gWb1,
              const float* __restrict__ gbb1,const float* __restrict__ gWb2,
              const float* __restrict__ gbb2,
              float* __restrict__ out_state,
              float* __restrict__ out_y,
              int T)   // T = B/2 (stride between row groups)
{
    __shared__ __align__(16) float ws[W_TOTAL];

    // ---- Stage weights as duplicated pairs ----
    for (int idx = threadIdx.x; idx < 64 * 12; idx += NTHREADS) {
        int r = idx / 12, c = idx % 12;
        float v = (c < 10) ? gW1[r * 10 + c] : (c == 10 ? gb1[r] : 0.0f);
        ws[W1D + r * 24 + 2 * c] = v;
        ws[W1D + r * 24 + 2 * c + 1] = v;
    }
    for (int idx = threadIdx.x; idx < 64 * 4; idx += NTHREADS) {
        int j = idx / 4, o = idx % 4;
        float v = gW2[o * HIDL + j];
        ws[W2TD + j * 8 + 2 * o] = v;
        ws[W2TD + j * 8 + 2 * o + 1] = v;
    }
    for (int idx = threadIdx.x; idx < 7 * 12; idx += NTHREADS) {
        int r = idx / 12, c = idx % 12;
        float v = (c < 10) ? gWz[r * 10 + c] : (c == 10 ? gbz[r] : 0.0f);
        ws[WZD + r * 24 + 2 * c] = v;
        ws[WZD + r * 24 + 2 * c + 1] = v;
    }
    for (int idx = threadIdx.x; idx < 96 * 8; idx += NTHREADS) {
        int r = idx / 8, c = idx % 8;
        float v = (c < 6) ? gWb1[r * 6 + c] : (c == 6 ? gbb1[r] : gWb2[r]);
        ws[WB1D + r * 16 + 2 * c] = v;
        ws[WB1D + r * 16 + 2 * c + 1] = v;
    }
    for (int idx = threadIdx.x; idx < 3 * 6; idx += NTHREADS) {
        int r = idx / 6, c = idx % 6;
        float v = (c < 3) ? gA[r * 3 + c] : gBm[r * 3 + (c - 3)];
        ws[PHYSD + r * 12 + 2 * c] = v;
        ws[PHYSD + r * 12 + 2 * c + 1] = v;
    }
    for (int idx = threadIdx.x; idx < 3 * 4; idx += NTHREADS) {
        int r = idx / 4, c = idx % 4;
        float v = (c < 3) ? gC[r * 3 + c] : 0.0f;
        ws[CD + r * 8 + 2 * c] = v;
        ws[CD + r * 8 + 2 * c + 1] = v;
    }
    for (int idx = threadIdx.x; idx < 4; idx += NTHREADS) {
        ws[B2D + 2 * idx] = gb2[idx];
        ws[B2D + 2 * idx + 1] = gb2[idx];
    }
    for (int idx = threadIdx.x; idx < 3; idx += NTHREADS) {
        ws[BB2D + 2 * idx] = gbb2[idx];
        ws[BB2D + 2 * idx + 1] = gbb2[idx];
    }
    __syncthreads();

    int t = blockIdx.x * NTHREADS + threadIdx.x;
    if (t >= T) return;
    // 2 rows per thread, packed as one f32x2 pair; fully coalesced.
    int r0 = t, r1 = t + T;

    // ---- Load su pair ----
    u64 su[SUDIM];
    #pragma unroll
    for (int i = 0; i < TOT; i++) {
        su[i] = pack2(__ldg(state + (size_t)r0 * TOT + i),
                      __ldg(state + (size_t)r1 * TOT + i));
    }
    #pragma unroll
    for (int i = 0; i < IDIM; i++) {
        su[TOT + i] = pack2(__ldg(u + (size_t)r0 * IDIM + i),
                            __ldg(u + (size_t)r1 * IDIM + i));
    }

    const u64 DT2 = pack2(DT_F, DT_F);
    u64 cand[TOT];

    // ---- Physics: cand[0..2] = s + DT*(A s + Bm u) ----
    {
        const ulonglong2* ph = (const ulonglong2*)(ws + PHYSD);
        #pragma unroll
        for (int i = 0; i < SDIM; i++) {
            ulonglong2 v0 = ph[i * 3 + 0], v1 = ph[i * 3 + 1], v2 = ph[i * 3 + 2];
            u64 d = 0ull;
            d = ffma2(v0.x, su[0], d);
            d = ffma2(v0.y, su[1], d);
            d = ffma2(v1.x, su[2], d);
            d = ffma2(v1.y, su[7], d);
            d = ffma2(v2.x, su[8], d);
            d = ffma2(v2.y, su[9], d);
            cand[i] = ffma2(DT2, d, su[i]);
        }
    }

    // ---- Latent MLP: acc = b2 + W2 tanh(W1 su + b1); cand[3..6] ----
    {
        const ulonglong2* w1r = (const ulonglong2*)(ws + W1D);
        const ulonglong2* w2r = (const ulonglong2*)(ws + W2TD);
        u64 acc0 = *(const u64*)(ws + B2D + 0);
        u64 acc1 = *(const u64*)(ws + B2D + 2);
        u64 acc2 = *(const u64*)(ws + B2D + 4);
        u64 acc3 = *(const u64*)(ws + B2D + 6);
        #pragma unroll 4
        for (int j = 0; j < HIDL; j++) {
            ulonglong2 q0 = w1r[j * 6 + 0], q1 = w1r[j * 6 + 1];
            ulonglong2 q2 = w1r[j * 6 + 2], q3 = w1r[j * 6 + 3];
            ulonglong2 q4 = w1r[j * 6 + 4], q5 = w1r[j * 6 + 5];
            u64 tA = q5.x;
            tA = ffma2(q0.x, su[0], tA);
            tA = ffma2(q0.y, su[1], tA);
            tA = ffma2(q1.x, su[2], tA);
            tA = ffma2(q1.y, su[3], tA);
            tA = ffma2(q2.x, su[4], tA);
            tA = ffma2(q2.y, su[5], tA);
            tA = ffma2(q3.x, su[6], tA);
            tA = ffma2(q3.y, su[7], tA);
            tA = ffma2(q4.x, su[8], tA);
            tA = ffma2(q4.y, su[9], tA);
            u64 h = tanh2(tA);
            ulonglong2 p0 = w2r[j * 2 + 0], p1 = w2r[j * 2 + 1];
            acc0 = ffma2(p0.x, h, acc0);
            acc1 = ffma2(p0.y, h, acc1);
            acc2 = ffma2(p1.x, h, acc2);
            acc3 = ffma2(p1.y, h, acc3);
        }
        cand[SDIM + 0] = ffma2(DT2, acc0, su[SDIM + 0]);
        cand[SDIM + 1] = ffma2(DT2, acc1, su[SDIM + 1]);
        cand[SDIM + 2] = ffma2(DT2, acc2, su[SDIM + 2]);
        cand[SDIM + 3] = ffma2(DT2, acc3, su[SDIM + 3]);
    }

    // ---- Gate + store next_state ----
    {
        const ulonglong2* wzr = (const ulonglong2*)(ws + WZD);
        #pragma unroll
        for (int i = 0; i < TOT; i++) {
            ulonglong2 q0 = wzr[i * 6 + 0], q1 = wzr[i * 6 + 1];
            ulonglong2 q2 = wzr[i * 6 + 2], q3 = wzr[i * 6 + 3];
            ulonglong2 q4 = wzr[i * 6 + 4], q5 = wzr[i * 6 + 5];
            u64 a = q5.x;
            a = ffma2(q0.x, su[0], a);
            a = ffma2(q0.y, su[1], a);
            a = ffma2(q1.x, su[2], a);
            a = ffma2(q1.y, su[3], a);
            a = ffma2(q2.x, su[4], a);
            a = ffma2(q2.y, su[5], a);
            a = ffma2(q3.x, su[6], a);
            a = ffma2(q3.y, su[7], a);
            a = ffma2(q4.x, su[8], a);
            a = ffma2(q4.y, su[9], a);

            float a0, a1, c0, c1, s0, s1;
            unpack2(a, a0, a1);
            unpack2(cand[i], c0, c1);
            unpack2(su[i], s0, s1);
            float z0 = fmaf(0.5f, fast_tanh(0.5f * a0), 0.5f);
            float z1 = fmaf(0.5f, fast_tanh(0.5f * a1), 0.5f);
            out_state[(size_t)r0 * TOT + i] = fmaf(z0, c0 - s0, s0);
            out_state[(size_t)r1 * TOT + i] = fmaf(z1, c1 - s1, s1);
        }
    }

    // ---- Residual branches + y_phys + store y ----
    {
        const ulonglong2* wbr = (const ulonglong2*)(ws + WB1D);
        const ulonglong2* cdp = (const ulonglong2*)(ws + CD);
        #pragma unroll
        for (int k = 0; k < SDIM; k++) {
            u64 res = 0ull;
            #pragma unroll 4
            for (int j = 0; j < HIDB; j++) {
                int r = k * HIDB + j;
                ulonglong2 v0 = wbr[r * 4 + 0], v1 = wbr[r * 4 + 1];
                ulonglong2 v2 = wbr[r * 4 + 2], v3 = wbr[r * 4 + 3];
                u64 tA = v3.x;
                tA = ffma2(v0.x, su[0], tA);
                tA = ffma2(v0.y, su[1], tA);
                tA = ffma2(v1.x, su[2], tA);
                tA = ffma2(v1.y, su[7], tA);
                tA = ffma2(v2.x, su[8], tA);
                tA = ffma2(v2.y, su[9], tA);
                res = ffma2(v3.y, tanh2(tA), res);
            }
            ulonglong2 c0 = cdp[k * 2 + 0], c1 = cdp[k * 2 + 1];
            u64 y = *(const u64*)(ws + BB2D + 2 * k);
            y = ffma2(c0.x, su[0], y);
            y = ffma2(c0.y, su[1], y);
            y = ffma2(c1.x, su[2], y);
            float y0, y1, e0, e1;
            unpack2(y, y0, y1);
            unpack2(res, e0, e1);
            out_y[(size_t)r0 * SDIM + k] = y0 + e0;
            out_y[(size_t)r1 * SDIM + k] = y1 + e1;
        }
    }
}

extern "C" void kernel_launch(void* const* d_in, const int* in_sizes, int n_in,
                              void* d_out, int out_size) {
    const float* state = (const float*)d_in[0];
    const float* u     = (const float*)d_in[1];
    const float* A     = (const float*)d_in[2];
    const float* Bm    = (const float*)d_in[3];
    const float* C     = (const float*)d_in[4];
    const float* Wz    = (const float*)d_in[5];
    const float* bz    = (const float*)d_in[6];
    const float* W1    = (const float*)d_in[7];
    const float* b1    = (const float*)d_in[8];
    const float* W2    = (const float*)d_in[9];
    const float* b2    = (const float*)d_in[10];
    const float* Wb1   = (const float*)d_in[11];
    const float* bb1   = (const float*)d_in[12];
    const float* Wb2   = (const float*)d_in[13];
    const float* bb2   = (const float*)d_in[14];

    int B = in_sizes[0] / TOT;
    int T = B / 2;                       // rows per group (B = 2^21, divisible)
    float* out       = (float*)d_out;
    float* out_state = out;              // [B, 7]
    float* out_y     = out + (size_t)B * TOT;  // [B, 3]

    int grid = (T + NTHREADS - 1) / NTHREADS;
    phygru_kernel<<<grid, NTHREADS>>>(state, u, A, Bm, C, Wz, bz, W1, b1,
                                      W2, b2, Wb1, bb1, Wb2, bb2,
                                      out_state, out_y, T);
}

// round 4
// speedup vs baseline: 1.2469x; 1.2469x over previous
#include <cuda_runtime.h>

typedef unsigned long long u64;

#define NTHREADS 128

#define SDIM   3
#define LDIM   4
#define IDIM   3
#define TOT    7
#define SUDIM  10
#define HIDL   64
#define HIDB   32
#define DT_F   0.01f

__device__ __forceinline__ u64 pack2(float lo, float hi) {
    u64 r; asm("mov.b64 %0, {%1, %2};" : "=l"(r) : "f"(lo), "f"(hi)); return r;
}
__device__ __forceinline__ void unpack2(u64 v, float& lo, float& hi) {
    asm("mov.b64 {%0, %1}, %2;" : "=f"(lo), "=f"(hi) : "l"(v));
}
__device__ __forceinline__ u64 ffma2(u64 a, u64 b, u64 c) {
    u64 d; asm("fma.rn.f32x2 %0, %1, %2, %3;" : "=l"(d) : "l"(a), "l"(b), "l"(c));
    return d;
}
__device__ __forceinline__ float fast_tanh(float x) {
    float r; asm("tanh.approx.f32 %0, %1;" : "=f"(r) : "f"(x)); return r;
}
__device__ __forceinline__ u64 tanh2(u64 v) {
    float lo, hi; unpack2(v, lo, hi);
    return pack2(fast_tanh(lo), fast_tanh(hi));
}
__device__ __forceinline__ float hsum(u64 v) {
    float lo, hi; unpack2(v, lo, hi); return lo + hi;
}

// ============================================================================
// Kernel A: next_state  (k-pack raw weight layout, 2 rows/thread)
// ============================================================================
// smem floats:
#define A_W1K   0      // 64 x 12: [w0..w9, b1, 0]
#define A_W2P   768    // 32 j-pairs x 8: [(W2[0][j],W2[0][j+1]) ... o=0..3]
#define A_WZK   1024   // 7 x 12: [w0..w9, bz, 0]
#define A_PHYS  1120   // 3 x 8: [a0,a1,a2,bm0,bm1,bm2,0,0]
#define A_B2P   1144   // 4 x 2: [(b2_o, 0)]
#define A_TOTAL 1152

__global__ void __launch_bounds__(NTHREADS, 5)
state_kernel(const float* __restrict__ state,
             const float* __restrict__ u,
             const float* __restrict__ gA,  const float* __restrict__ gBm,
             const float* __restrict__ gWz, const float* __restrict__ gbz,
             const float* __restrict__ gW1, const float* __restrict__ gb1,
             const float* __restrict__ gW2, const float* __restrict__ gb2,
             float* __restrict__ out_state,
             int T)   // T = B/2
{
    __shared__ __align__(16) float ws[A_TOTAL];

    for (int idx = threadIdx.x; idx < 64 * 12; idx += NTHREADS) {
        int r = idx / 12, c = idx % 12;
        ws[A_W1K + idx] = (c < 10) ? gW1[r * 10 + c] : (c == 10 ? gb1[r] : 0.0f);
    }
    for (int idx = threadIdx.x; idx < 32 * 8; idx += NTHREADS) {
        int p = idx / 8, c = idx % 8;
        int o = c >> 1, j = 2 * p + (c & 1);
        ws[A_W2P + idx] = gW2[o * HIDL + j];
    }
    for (int idx = threadIdx.x; idx < 7 * 12; idx += NTHREADS) {
        int r = idx / 12, c = idx % 12;
        ws[A_WZK + idx] = (c < 10) ? gWz[r * 10 + c] : (c == 10 ? gbz[r] : 0.0f);
    }
    for (int idx = threadIdx.x; idx < 3 * 8; idx += NTHREADS) {
        int r = idx / 8, c = idx % 8;
        float v = 0.0f;
        if (c < 3) v = gA[r * 3 + c];
        else if (c < 6) v = gBm[r * 3 + (c - 3)];
        ws[A_PHYS + idx] = v;
    }
    for (int idx = threadIdx.x; idx < 8; idx += NTHREADS) {
        ws[A_B2P + idx] = (idx & 1) ? 0.0f : gb2[idx >> 1];
    }
    __syncthreads();

    int t = blockIdx.x * NTHREADS + threadIdx.x;
    if (t >= T) return;
    int r0 = t, r1 = t + T;

    // su per row (scalars; pairs built once, unpack is free)
    float s0[SUDIM], s1[SUDIM];
    #pragma unroll
    for (int i = 0; i < TOT; i++) {
        s0[i] = __ldg(state + (size_t)r0 * TOT + i);
        s1[i] = __ldg(state + (size_t)r1 * TOT + i);
    }
    #pragma unroll
    for (int i = 0; i < IDIM; i++) {
        s0[TOT + i] = __ldg(u + (size_t)r0 * IDIM + i);
        s1[TOT + i] = __ldg(u + (size_t)r1 * IDIM + i);
    }
    u64 sp0[5], sp1[5];
    #pragma unroll
    for (int k = 0; k < 5; k++) {
        sp0[k] = pack2(s0[2 * k], s0[2 * k + 1]);
        sp1[k] = pack2(s1[2 * k], s1[2 * k + 1]);
    }
    // phys input pairs: (s0,s1)=sp[0], (s2,u0), (u1,u2)=sp[4]
    u64 pv0_m = pack2(s0[2], s0[7]);
    u64 pv1_m = pack2(s1[2], s1[7]);

    float cand0[TOT], cand1[TOT];

    // ---- Physics ----
    {
        const ulonglong2* ph = (const ulonglong2*)(ws + A_PHYS);
        #pragma unroll
        for (int i = 0; i < SDIM; i++) {
            ulonglong2 q0 = ph[i * 2 + 0], q1 = ph[i * 2 + 1];
            u64 d0 = ffma2(q1.x, sp0[4], 0ull);
            u64 d1 = ffma2(q1.x, sp1[4], 0ull);
            d0 = ffma2(q0.y, pv0_m, d0);
            d1 = ffma2(q0.y, pv1_m, d1);
            d0 = ffma2(q0.x, sp0[0], d0);
            d1 = ffma2(q0.x, sp1[0], d1);
            cand0[i] = fmaf(DT_F, hsum(d0), s0[i]);
            cand1[i] = fmaf(DT_F, hsum(d1), s1[i]);
        }
    }

    // ---- Latent MLP (j-pairs, 4 independent chains per iteration) ----
    {
        const ulonglong2* w1r = (const ulonglong2*)(ws + A_W1K);
        const ulonglong2* w2p = (const ulonglong2*)(ws + A_W2P);
        u64 acc0[LDIM], acc1[LDIM];
        #pragma unroll
        for (int o = 0; o < LDIM; o++) {
            u64 b = *(const u64*)(ws + A_B2P + 2 * o);
            acc0[o] = b; acc1[o] = b;
        }
        #pragma unroll 4
        for (int p = 0; p < HIDL / 2; p++) {
            int ja = 2 * p, jb = 2 * p + 1;
            ulonglong2 qa0 = w1r[ja * 3 + 0], qa1 = w1r[ja * 3 + 1], qa2 = w1r[ja * 3 + 2];
            ulonglong2 qb0 = w1r[jb * 3 + 0], qb1 = w1r[jb * 3 + 1], qb2 = w1r[jb * 3 + 2];
            // chains: (row0,ja) (row0,jb) (row1,ja) (row1,jb)
            u64 ta0 = qa2.y, tb0 = qb2.y, ta1 = qa2.y, tb1 = qb2.y;
            ta0 = ffma2(qa0.x, sp0[0], ta0);  tb0 = ffma2(qb0.x, sp0[0], tb0);
            ta1 = ffma2(qa0.x, sp1[0], ta1);  tb1 = ffma2(qb0.x, sp1[0], tb1);
            ta0 = ffma2(qa0.y, sp0[1], ta0);  tb0 = ffma2(qb0.y, sp0[1], tb0);
            ta1 = ffma2(qa0.y, sp1[1], ta1);  tb1 = ffma2(qb0.y, sp1[1], tb1);
            ta0 = ffma2(qa1.x, sp0[2], ta0);  tb0 = ffma2(qb1.x, sp0[2], tb0);
            ta1 = ffma2(qa1.x, sp1[2], ta1);  tb1 = ffma2(qb1.x, sp1[2], tb1);
            ta0 = ffma2(qa1.y, sp0[3], ta0);  tb0 = ffma2(qb1.y, sp0[3], tb0);
            ta1 = ffma2(qa1.y, sp1[3], ta1);  tb1 = ffma2(qb1.y, sp1[3], tb1);
            ta0 = ffma2(qa2.x, sp0[4], ta0);  tb0 = ffma2(qb2.x, sp0[4], tb0);
            ta1 = ffma2(qa2.x, sp1[4], ta1);  tb1 = ffma2(qb2.x, sp1[4], tb1);
            u64 hp0 = pack2(fast_tanh(hsum(ta0)), fast_tanh(hsum(tb0)));
            u64 hp1 = pack2(fast_tanh(hsum(ta1)), fast_tanh(hsum(tb1)));
            ulonglong2 p0 = w2p[p * 2 + 0], p1 = w2p[p * 2 + 1];
            acc0[0] = ffma2(p0.x, hp0, acc0[0]);  acc1[0] = ffma2(p0.x, hp1, acc1[0]);
            acc0[1] = ffma2(p0.y, hp0, acc0[1]);  acc1[1] = ffma2(p0.y, hp1, acc1[1]);
            acc0[2] = ffma2(p1.x, hp0, acc0[2]);  acc1[2] = ffma2(p1.x, hp1, acc1[2]);
            acc0[3] = ffma2(p1.y, hp0, acc0[3]);  acc1[3] = ffma2(p1.y, hp1, acc1[3]);
        }
        #pragma unroll
        for (int o = 0; o < LDIM; o++) {
            cand0[SDIM + o] = fmaf(DT_F, hsum(acc0[o]), s0[SDIM + o]);
            cand1[SDIM + o] = fmaf(DT_F, hsum(acc1[o]), s1[SDIM + o]);
        }
    }

    // ---- Gate + store ----
    {
        const ulonglong2* wzr = (const ulonglong2*)(ws + A_WZK);
        #pragma unroll
        for (int i = 0; i < TOT; i++) {
            ulonglong2 q0 = wzr[i * 3 + 0], q1 = wzr[i * 3 + 1], q2 = wzr[i * 3 + 2];
            u64 t0 = q2.y, t1 = q2.y;
            t0 = ffma2(q0.x, sp0[0], t0);  t1 = ffma2(q0.x, sp1[0], t1);
            t0 = ffma2(q0.y, sp0[1], t0);  t1 = ffma2(q0.y, sp1[1], t1);
            t0 = ffma2(q1.x, sp0[2], t0);  t1 = ffma2(q1.x, sp1[2], t1);
            t0 = ffma2(q1.y, sp0[3], t0);  t1 = ffma2(q1.y, sp1[3], t1);
            t0 = ffma2(q2.x, sp0[4], t0);  t1 = ffma2(q2.x, sp1[4], t1);
            float z0 = fmaf(0.5f, fast_tanh(0.5f * hsum(t0)), 0.5f);
            float z1 = fmaf(0.5f, fast_tanh(0.5f * hsum(t1)), 0.5f);
            out_state[(size_t)r0 * TOT + i] = fmaf(z0, cand0[i] - s0[i], s0[i]);
            out_state[(size_t)r1 * TOT + i] = fmaf(z1, cand1[i] - s1[i], s1[i]);
        }
    }
}

// ============================================================================
// Kernel B: y  (duplicated-pair layout, 4 rows/thread)
// ============================================================================
// smem floats:
#define B_WB1D  0      // 96 rows x 16: [6 w-pairs][bb1 pair][wb2 pair]
#define B_CD    1536   // 3 rows x 8:  [C row 3 pairs][zero pad pair]
#define B_BB2D  1560   // 3 pairs
#define B_TOTAL 1568

__global__ void __launch_bounds__(NTHREADS, 7)
y_kernel(const float* __restrict__ state,
         const float* __restrict__ u,
         const float* __restrict__ gC,
         const float* __restrict__ gWb1, const float* __restrict__ gbb1,
         const float* __restrict__ gWb2, const float* __restrict__ gbb2,
         float* __restrict__ out_y,
         int T)   // T = B/4
{
    __shared__ __align__(16) float ws[B_TOTAL];

    for (int idx = threadIdx.x; idx < 96 * 8; idx += NTHREADS) {
        int r = idx / 8, c = idx % 8;
        float v = (c < 6) ? gWb1[r * 6 + c] : (c == 6 ? gbb1[r] : gWb2[r]);
        ws[B_WB1D + r * 16 + 2 * c] = v;
        ws[B_WB1D + r * 16 + 2 * c + 1] = v;
    }
    for (int idx = threadIdx.x; idx < 3 * 4; idx += NTHREADS) {
        int r = idx / 4, c = idx % 4;
        float v = (c < 3) ? gC[r * 3 + c] : 0.0f;
        ws[B_CD + r * 8 + 2 * c] = v;
        ws[B_CD + r * 8 + 2 * c + 1] = v;
    }
    for (int idx = threadIdx.x; idx < 3; idx += NTHREADS) {
        ws[B_BB2D + 2 * idx] = gbb2[idx];
        ws[B_BB2D + 2 * idx + 1] = gbb2[idx];
    }
    __syncthreads();

    int t = blockIdx.x * NTHREADS + threadIdx.x;
    if (t >= T) return;
    int r0 = t, r1 = t + T, r2 = t + 2 * T, r3 = t + 3 * T;

    // branch inputs: [s0,s1,s2,u0,u1,u2], packed over row pairs
    u64 biA[6], biB[6];
    #pragma unroll
    for (int i = 0; i < SDIM; i++) {
        biA[i] = pack2(__ldg(state + (size_t)r0 * TOT + i),
                       __ldg(state + (size_t)r1 * TOT + i));
        biB[i] = pack2(__ldg(state + (size_t)r2 * TOT + i),
                       __ldg(state + (size_t)r3 * TOT + i));
    }
    #pragma unroll
    for (int i = 0; i < IDIM; i++) {
        biA[SDIM + i] = pack2(__ldg(u + (size_t)r0 * IDIM + i),
                              __ldg(u + (size_t)r1 * IDIM + i));
        biB[SDIM + i] = pack2(__ldg(u + (size_t)r2 * IDIM + i),
                              __ldg(u + (size_t)r3 * IDIM + i));
    }

    const ulonglong2* wbr = (const ulonglong2*)(ws + B_WB1D);
    const ulonglong2* cdp = (const ulonglong2*)(ws + B_CD);

    #pragma unroll
    for (int k = 0; k < SDIM; k++) {
        u64 resA = 0ull, resB = 0ull;
        #pragma unroll 4
        for (int j = 0; j < HIDB; j++) {
            int r = k * HIDB + j;
            ulonglong2 v0 = wbr[r * 4 + 0], v1 = wbr[r * 4 + 1];
            ulonglong2 v2 = wbr[r * 4 + 2], v3 = wbr[r * 4 + 3];
            u64 tA = v3.x, tB = v3.x;
            tA = ffma2(v0.x, biA[0], tA);  tB = ffma2(v0.x, biB[0], tB);
            tA = ffma2(v0.y, biA[1], tA);  tB = ffma2(v0.y, biB[1], tB);
            tA = ffma2(v1.x, biA[2], tA);  tB = ffma2(v1.x, biB[2], tB);
            tA = ffma2(v1.y, biA[3], tA);  tB = ffma2(v1.y, biB[3], tB);
            tA = ffma2(v2.x, biA[4], tA);  tB = ffma2(v2.x, biB[4], tB);
            tA = ffma2(v2.y, biA[5], tA);  tB = ffma2(v2.y, biB[5], tB);
            resA = ffma2(v3.y, tanh2(tA), resA);
            resB = ffma2(v3.y, tanh2(tB), resB);
        }
        ulonglong2 c0 = cdp[k * 2 + 0], c1 = cdp[k * 2 + 1];
        u64 yA = *(const u64*)(ws + B_BB2D + 2 * k);
        u64 yB = yA;
        yA = ffma2(c0.x, biA[0], yA);  yB = ffma2(c0.x, biB[0], yB);
        yA = ffma2(c0.y, biA[1], yA);  yB = ffma2(c0.y, biB[1], yB);
        yA = ffma2(c1.x, biA[2], yA);  yB = ffma2(c1.x, biB[2], yB);
        float y0, y1, y2, y3, e0, e1, e2, e3;
        unpack2(yA, y0, y1);  unpack2(yB, y2, y3);
        unpack2(resA, e0, e1);  unpack2(resB, e2, e3);
        out_y[(size_t)r0 * SDIM + k] = y0 + e0;
        out_y[(size_t)r1 * SDIM + k] = y1 + e1;
        out_y[(size_t)r2 * SDIM + k] = y2 + e2;
        out_y[(size_t)r3 * SDIM + k] = y3 + e3;
    }
}

extern "C" void kernel_launch(void* const* d_in, const int* in_sizes, int n_in,
                              void* d_out, int out_size) {
    const float* state = (const float*)d_in[0];
    const float* u     = (const float*)d_in[1];
    const float* A     = (const float*)d_in[2];
    const float* Bm    = (const float*)d_in[3];
    const float* C     = (const float*)d_in[4];
    const float* Wz    = (const float*)d_in[5];
    const float* bz    = (const float*)d_in[6];
    const float* W1    = (const float*)d_in[7];
    const float* b1    = (const float*)d_in[8];
    const float* W2    = (const float*)d_in[9];
    const float* b2    = (const float*)d_in[10];
    const float* Wb1   = (const float*)d_in[11];
    const float* bb1   = (const float*)d_in[12];
    const float* Wb2   = (const float*)d_in[13];
    const float* bb2   = (const float*)d_in[14];

    int B = in_sizes[0] / TOT;
    float* out       = (float*)d_out;
    float* out_state = out;                      // [B, 7]
    float* out_y     = out + (size_t)B * TOT;    // [B, 3]

    int Ts = B / 2;
    int grid_s = (Ts + NTHREADS - 1) / NTHREADS;
    state_kernel<<<grid_s, NTHREADS>>>(state, u, A, Bm, Wz, bz, W1, b1, W2, b2,
                                       out_state, Ts);

    int Ty = B / 4;
    int grid_y = (Ty + NTHREADS - 1) / NTHREADS;
    y_kernel<<<grid_y, NTHREADS>>>(state, u, C, Wb1, bb1, Wb2, bb2, out_y, Ty);
}

// round 5
// speedup vs baseline: 1.2643x; 1.0140x over previous
#include <cuda_runtime.h>

typedef unsigned long long u64;

#define NTHREADS 128

#define SDIM   3
#define LDIM   4
#define IDIM   3
#define TOT    7
#define SUDIM  10
#define HIDL   64
#define HIDB   32
#define DT_F   0.01f

__device__ __forceinline__ u64 pack2(float lo, float hi) {
    u64 r; asm("mov.b64 %0, {%1, %2};" : "=l"(r) : "f"(lo), "f"(hi)); return r;
}
__device__ __forceinline__ void unpack2(u64 v, float& lo, float& hi) {
    asm("mov.b64 {%0, %1}, %2;" : "=f"(lo), "=f"(hi) : "l"(v));
}
__device__ __forceinline__ u64 ffma2(u64 a, u64 b, u64 c) {
    u64 d; asm("fma.rn.f32x2 %0, %1, %2, %3;" : "=l"(d) : "l"(a), "l"(b), "l"(c));
    return d;
}
__device__ __forceinline__ float fast_tanh(float x) {
    float r; asm("tanh.approx.f32 %0, %1;" : "=f"(r) : "f"(x)); return r;
}
__device__ __forceinline__ u64 tanh2(u64 v) {
    float lo, hi; unpack2(v, lo, hi);
    return pack2(fast_tanh(lo), fast_tanh(hi));
}
__device__ __forceinline__ float hsum(u64 v) {
    float lo, hi; unpack2(v, lo, hi); return lo + hi;
}
__device__ __forceinline__ float getlo(u64 v) {
    float lo, hi; unpack2(v, lo, hi); return lo;
}
__device__ __forceinline__ float gethi(u64 v) {
    float lo, hi; unpack2(v, lo, hi); return hi;
}

// ============================================================================
// Kernel A: next_state  (k-pack raw weight layout, 2 rows/thread)
// ============================================================================
#define A_W1K   0      // 64 x 12: [w0..w9, b1, 0]
#define A_W2P   768    // 32 j-pairs x 8: [(W2[o][2p],W2[o][2p+1]) for o=0..3]
#define A_WZK   1024   // 7 x 12: [w0..w9, bz, 0]
#define A_PHYS  1120   // 3 x 8: [a0,a1,a2,bm0,bm1,bm2,0,0]
#define A_B2S   1144   // 4 scalars
#define A_TOTAL 1148

__global__ void __launch_bounds__(NTHREADS, 7)
state_kernel(const float* __restrict__ state,
             const float* __restrict__ u,
             const float* __restrict__ gA,  const float* __restrict__ gBm,
             const float* __restrict__ gWz, const float* __restrict__ gbz,
             const float* __restrict__ gW1, const float* __restrict__ gb1,
             const float* __restrict__ gW2, const float* __restrict__ gb2,
             float* __restrict__ out_state,
             int T)   // T = B/2
{
    __shared__ __align__(16) float ws[A_TOTAL];

    for (int idx = threadIdx.x; idx < 64 * 12; idx += NTHREADS) {
        int r = idx / 12, c = idx % 12;
        ws[A_W1K + idx] = (c < 10) ? gW1[r * 10 + c] : (c == 10 ? gb1[r] : 0.0f);
    }
    for (int idx = threadIdx.x; idx < 32 * 8; idx += NTHREADS) {
        int p = idx / 8, c = idx % 8;
        int o = c >> 1, j = 2 * p + (c & 1);
        ws[A_W2P + idx] = gW2[o * HIDL + j];
    }
    for (int idx = threadIdx.x; idx < 7 * 12; idx += NTHREADS) {
        int r = idx / 12, c = idx % 12;
        ws[A_WZK + idx] = (c < 10) ? gWz[r * 10 + c] : (c == 10 ? gbz[r] : 0.0f);
    }
    for (int idx = threadIdx.x; idx < 3 * 8; idx += NTHREADS) {
        int r = idx / 8, c = idx % 8;
        float v = 0.0f;
        if (c < 3) v = gA[r * 3 + c];
        else if (c < 6) v = gBm[r * 3 + (c - 3)];
        ws[A_PHYS + idx] = v;
    }
    for (int idx = threadIdx.x; idx < 4; idx += NTHREADS)
        ws[A_B2S + idx] = gb2[idx];
    __syncthreads();

    int t = blockIdx.x * NTHREADS + threadIdx.x;
    if (t >= T) return;
    int r0 = t, r1 = t + T;

    // su pairs only (within-row packing): sp[k] = (su[2k], su[2k+1])
    u64 sp0[5], sp1[5];
    {
        const float* s0p = state + (size_t)r0 * TOT;
        const float* s1p = state + (size_t)r1 * TOT;
        const float* u0p = u + (size_t)r0 * IDIM;
        const float* u1p = u + (size_t)r1 * IDIM;
        sp0[0] = pack2(__ldg(s0p + 0), __ldg(s0p + 1));
        sp0[1] = pack2(__ldg(s0p + 2), __ldg(s0p + 3));
        sp0[2] = pack2(__ldg(s0p + 4), __ldg(s0p + 5));
        sp0[3] = pack2(__ldg(s0p + 6), __ldg(u0p + 0));
        sp0[4] = pack2(__ldg(u0p + 1), __ldg(u0p + 2));
        sp1[0] = pack2(__ldg(s1p + 0), __ldg(s1p + 1));
        sp1[1] = pack2(__ldg(s1p + 2), __ldg(s1p + 3));
        sp1[2] = pack2(__ldg(s1p + 4), __ldg(s1p + 5));
        sp1[3] = pack2(__ldg(s1p + 6), __ldg(u1p + 0));
        sp1[4] = pack2(__ldg(u1p + 1), __ldg(u1p + 2));
    }

    // ---- Phase 1: gate pre-acts + sigmoid (MUFU issued early) ----
    float z0[TOT], z1[TOT];
    {
        const ulonglong2* wzr = (const ulonglong2*)(ws + A_WZK);
        #pragma unroll
        for (int i = 0; i < TOT; i++) {
            ulonglong2 q0 = wzr[i * 3 + 0], q1 = wzr[i * 3 + 1], q2 = wzr[i * 3 + 2];
            u64 t0 = q2.y, t1 = q2.y;   // (bz, 0)
            t0 = ffma2(q0.x, sp0[0], t0);  t1 = ffma2(q0.x, sp1[0], t1);
            t0 = ffma2(q0.y, sp0[1], t0);  t1 = ffma2(q0.y, sp1[1], t1);
            t0 = ffma2(q1.x, sp0[2], t0);  t1 = ffma2(q1.x, sp1[2], t1);
            t0 = ffma2(q1.y, sp0[3], t0);  t1 = ffma2(q1.y, sp1[3], t1);
            t0 = ffma2(q2.x, sp0[4], t0);  t1 = ffma2(q2.x, sp1[4], t1);
            z0[i] = fmaf(0.5f, fast_tanh(0.5f * hsum(t0)), 0.5f);
            z1[i] = fmaf(0.5f, fast_tanh(0.5f * hsum(t1)), 0.5f);
        }
    }

    // ---- Phase 2: physics candidates + immediate store of rows 0..2 ----
    {
        const ulonglong2* ph = (const ulonglong2*)(ws + A_PHYS);
        u64 pm0 = pack2(gethi(sp0[1]) * 0.0f + getlo(sp0[1]), gethi(sp0[3]));
        // pm = (su2, u0): su2 = sp[1].lo, u0 = sp[3].hi
        u64 pm1 = pack2(getlo(sp1[1]), gethi(sp1[3]));
        #pragma unroll
        for (int i = 0; i < SDIM; i++) {
            ulonglong2 q0 = ph[i * 2 + 0], q1 = ph[i * 2 + 1];
            u64 d0 = ffma2(q1.x, sp0[4], 0ull);
            u64 d1 = ffma2(q1.x, sp1[4], 0ull);
            d0 = ffma2(q0.y, pm0, d0);
            d1 = ffma2(q0.y, pm1, d1);
            d0 = ffma2(q0.x, sp0[0], d0);
            d1 = ffma2(q0.x, sp1[0], d1);
            float s0i = (i < 2) ? ((i == 0) ? getlo(sp0[0]) : gethi(sp0[0]))
                                : getlo(sp0[1]);
            float s1i = (i < 2) ? ((i == 0) ? getlo(sp1[0]) : gethi(sp1[0]))
                                : getlo(sp1[1]);
            float c0 = fmaf(DT_F, hsum(d0), s0i);
            float c1 = fmaf(DT_F, hsum(d1), s1i);
            out_state[(size_t)r0 * TOT + i] = fmaf(z0[i], c0 - s0i, s0i);
            out_state[(size_t)r1 * TOT + i] = fmaf(z1[i], c1 - s1i, s1i);
        }
    }

    // ---- Phase 3: latent MLP ----
    {
        const ulonglong2* w1r = (const ulonglong2*)(ws + A_W1K);
        const ulonglong2* w2p = (const ulonglong2*)(ws + A_W2P);
        u64 acc0[LDIM], acc1[LDIM];
        #pragma unroll
        for (int o = 0; o < LDIM; o++) { acc0[o] = 0ull; acc1[o] = 0ull; }
        #pragma unroll 2
        for (int p = 0; p < HIDL / 2; p++) {
            int ja = 2 * p, jb = 2 * p + 1;
            ulonglong2 qa0 = w1r[ja * 3 + 0], qa1 = w1r[ja * 3 + 1], qa2 = w1r[ja * 3 + 2];
            ulonglong2 qb0 = w1r[jb * 3 + 0], qb1 = w1r[jb * 3 + 1], qb2 = w1r[jb * 3 + 2];
            u64 ta0 = qa2.y, tb0 = qb2.y, ta1 = qa2.y, tb1 = qb2.y;
            ta0 = ffma2(qa0.x, sp0[0], ta0);  tb0 = ffma2(qb0.x, sp0[0], tb0);
            ta1 = ffma2(qa0.x, sp1[0], ta1);  tb1 = ffma2(qb0.x, sp1[0], tb1);
            ta0 = ffma2(qa0.y, sp0[1], ta0);  tb0 = ffma2(qb0.y, sp0[1], tb0);
            ta1 = ffma2(qa0.y, sp1[1], ta1);  tb1 = ffma2(qb0.y, sp1[1], tb1);
            ta0 = ffma2(qa1.x, sp0[2], ta0);  tb0 = ffma2(qb1.x, sp0[2], tb0);
            ta1 = ffma2(qa1.x, sp1[2], ta1);  tb1 = ffma2(qb1.x, sp1[2], tb1);
            ta0 = ffma2(qa1.y, sp0[3], ta0);  tb0 = ffma2(qb1.y, sp0[3], tb0);
            ta1 = ffma2(qa1.y, sp1[3], ta1);  tb1 = ffma2(qb1.y, sp1[3], tb1);
            ta0 = ffma2(qa2.x, sp0[4], ta0);  tb0 = ffma2(qb2.x, sp0[4], tb0);
            ta1 = ffma2(qa2.x, sp1[4], ta1);  tb1 = ffma2(qb2.x, sp1[4], tb1);
            u64 hp0 = pack2(fast_tanh(hsum(ta0)), fast_tanh(hsum(tb0)));
            u64 hp1 = pack2(fast_tanh(hsum(ta1)), fast_tanh(hsum(tb1)));
            ulonglong2 p0 = w2p[p * 2 + 0], p1 = w2p[p * 2 + 1];
            acc0[0] = ffma2(p0.x, hp0, acc0[0]);  acc1[0] = ffma2(p0.x, hp1, acc1[0]);
            acc0[1] = ffma2(p0.y, hp0, acc0[1]);  acc1[1] = ffma2(p0.y, hp1, acc1[1]);
            acc0[2] = ffma2(p1.x, hp0, acc0[2]);  acc1[2] = ffma2(p1.x, hp1, acc1[2]);
            acc0[3] = ffma2(p1.y, hp0, acc0[3]);  acc1[3] = ffma2(p1.y, hp1, acc1[3]);
        }
        // latent su values: su3 = sp[1].hi, su4 = sp[2].lo, su5 = sp[2].hi, su6 = sp[3].lo
        float l0[LDIM], l1[LDIM];
        l0[0] = gethi(sp0[1]); l0[1] = getlo(sp0[2]); l0[2] = gethi(sp0[2]); l0[3] = getlo(sp0[3]);
        l1[0] = gethi(sp1[1]); l1[1] = getlo(sp1[2]); l1[2] = gethi(sp1[2]); l1[3] = getlo(sp1[3]);
        #pragma unroll
        for (int o = 0; o < LDIM; o++) {
            float b2o = ws[A_B2S + o];
            float c0 = fmaf(DT_F, hsum(acc0[o]) + b2o, l0[o]);
            float c1 = fmaf(DT_F, hsum(acc1[o]) + b2o, l1[o]);
            int i = SDIM + o;
            out_state[(size_t)r0 * TOT + i] = fmaf(z0[i], c0 - l0[o], l0[o]);
            out_state[(size_t)r1 * TOT + i] = fmaf(z1[i], c1 - l1[o], l1[o]);
        }
    }
}

// ============================================================================
// Kernel B: y  (duplicated-pair layout, 4 rows/thread)
// ============================================================================
#define B_WB1D  0      // 96 rows x 16: [6 w-pairs][bb1 pair][wb2 pair]
#define B_CD    1536   // 3 rows x 8:  [C row 3 pairs][(bb2,bb2) pad pair]
#define B_TOTAL 1560

__global__ void __launch_bounds__(NTHREADS, 8)
y_kernel(const float* __restrict__ state,
         const float* __restrict__ u,
         const float* __restrict__ gC,
         const float* __restrict__ gWb1, const float* __restrict__ gbb1,
         const float* __restrict__ gWb2, const float* __restrict__ gbb2,
         float* __restrict__ out_y,
         int T)   // T = B/4
{
    __shared__ __align__(16) float ws[B_TOTAL];

    for (int idx = threadIdx.x; idx < 96 * 8; idx += NTHREADS) {
        int r = idx / 8, c = idx % 8;
        float v = (c < 6) ? gWb1[r * 6 + c] : (c == 6 ? gbb1[r] : gWb2[r]);
        ws[B_WB1D + r * 16 + 2 * c] = v;
        ws[B_WB1D + r * 16 + 2 * c + 1] = v;
    }
    for (int idx = threadIdx.x; idx < 3 * 4; idx += NTHREADS) {
        int r = idx / 4, c = idx % 4;
        float v = (c < 3) ? gC[r * 3 + c] : gbb2[r];
        ws[B_CD + r * 8 + 2 * c] = v;
        ws[B_CD + r * 8 + 2 * c + 1] = v;
    }
    __syncthreads();

    int t = blockIdx.x * NTHREADS + threadIdx.x;
    if (t >= T) return;
    int r0 = t, r1 = t + T, r2 = t + 2 * T, r3 = t + 3 * T;

    u64 biA[6], biB[6];
    #pragma unroll
    for (int i = 0; i < SDIM; i++) {
        biA[i] = pack2(__ldg(state + (size_t)r0 * TOT + i),
                       __ldg(state + (size_t)r1 * TOT + i));
        biB[i] = pack2(__ldg(state + (size_t)r2 * TOT + i),
                       __ldg(state + (size_t)r3 * TOT + i));
    }
    #pragma unroll
    for (int i = 0; i < IDIM; i++) {
        biA[SDIM + i] = pack2(__ldg(u + (size_t)r0 * IDIM + i),
                              __ldg(u + (size_t)r1 * IDIM + i));
        biB[SDIM + i] = pack2(__ldg(u + (size_t)r2 * IDIM + i),
                              __ldg(u + (size_t)r3 * IDIM + i));
    }

    const ulonglong2* wbr = (const ulonglong2*)(ws + B_WB1D);
    const ulonglong2* cdp = (const ulonglong2*)(ws + B_CD);

    #pragma unroll
    for (int k = 0; k < SDIM; k++) {
        // y_phys + bb2 first (short lifetime epilogue)
        ulonglong2 c0 = cdp[k * 2 + 0], c1 = cdp[k * 2 + 1];
        u64 resA = c1.y, resB = c1.y;       // start from (bb2, bb2)
        resA = ffma2(c0.x, biA[0], resA);  resB = ffma2(c0.x, biB[0], resB);
        resA = ffma2(c0.y, biA[1], resA);  resB = ffma2(c0.y, biB[1], resB);
        resA = ffma2(c1.x, biA[2], resA);  resB = ffma2(c1.x, biB[2], resB);
        #pragma unroll 4
        for (int j = 0; j < HIDB; j++) {
            int r = k * HIDB + j;
            ulonglong2 v0 = wbr[r * 4 + 0], v1 = wbr[r * 4 + 1];
            ulonglong2 v2 = wbr[r * 4 + 2], v3 = wbr[r * 4 + 3];
            u64 tA = v3.x, tB = v3.x;
            tA = ffma2(v0.x, biA[0], tA);  tB = ffma2(v0.x, biB[0], tB);
            tA = ffma2(v0.y, biA[1], tA);  tB = ffma2(v0.y, biB[1], tB);
            tA = ffma2(v1.x, biA[2], tA);  tB = ffma2(v1.x, biB[2], tB);
            tA = ffma2(v1.y, biA[3], tA);  tB = ffma2(v1.y, biB[3], tB);
            tA = ffma2(v2.x, biA[4], tA);  tB = ffma2(v2.x, biB[4], tB);
            tA = ffma2(v2.y, biA[5], tA);  tB = ffma2(v2.y, biB[5], tB);
            resA = ffma2(v3.y, tanh2(tA), resA);
            resB = ffma2(v3.y, tanh2(tB), resB);
        }
        float y0, y1, y2, y3;
        unpack2(resA, y0, y1);  unpack2(resB, y2, y3);
        out_y[(size_t)r0 * SDIM + k] = y0;
        out_y[(size_t)r1 * SDIM + k] = y1;
        out_y[(size_t)r2 * SDIM + k] = y2;
        out_y[(size_t)r3 * SDIM + k] = y3;
    }
}

extern "C" void kernel_launch(void* const* d_in, const int* in_sizes, int n_in,
                              void* d_out, int out_size) {
    const float* state = (const float*)d_in[0];
    const float* u     = (const float*)d_in[1];
    const float* A     = (const float*)d_in[2];
    const float* Bm    = (const float*)d_in[3];
    const float* C     = (const float*)d_in[4];
    const float* Wz    = (const float*)d_in[5];
    const float* bz    = (const float*)d_in[6];
    const float* W1    = (const float*)d_in[7];
    const float* b1    = (const float*)d_in[8];
    const float* W2    = (const float*)d_in[9];
    const float* b2    = (const float*)d_in[10];
    const float* Wb1   = (const float*)d_in[11];
    const float* bb1   = (const float*)d_in[12];
    const float* Wb2   = (const float*)d_in[13];
    const float* bb2   = (const float*)d_in[14];

    int B = in_sizes[0] / TOT;
    float* out       = (float*)d_out;
    float* out_state = out;                      // [B, 7]
    float* out_y     = out + (size_t)B * TOT;    // [B, 3]

    int Ts = B / 2;
    int grid_s = (Ts + NTHREADS - 1) / NTHREADS;
    state_kernel<<<grid_s, NTHREADS>>>(state, u, A, Bm, Wz, bz, W1, b1, W2, b2,
                                       out_state, Ts);

    int Ty = B / 4;
    int grid_y = (Ty + NTHREADS - 1) / NTHREADS;
    y_kernel<<<grid_y, NTHREADS>>>(state, u, C, Wb1, bb1, Wb2, bb2, out_y, Ty);
}